// round 4
// baseline (speedup 1.0000x reference)
#include <cuda_runtime.h>
#include <stdint.h>

#define D     10000
#define F     5001      // Hermitian bins 0..5000
#define NB    64
#define NS    128
#define NA    10
#define NR    8
#define NP    256
#define FFTTHREADS 1024
#define BG    16

// proj tiling
#define DSPLIT 125
#define DLEN   80       // D / DSPLIT

// skewed smem index: pad every 16 float2 (128B) to break conflicts
#define SK(i) ((i) + ((i) >> 4))
#define SBUF  10624      // SK(9999)+1

// ---------------- device scratch ----------------
__device__ float2 T_g[1000 * 10];     // T[j][t] = exp(-2*pi*i*j*t/D)
__device__ float2 Fa_g[NA * F];
__device__ float2 Fp_g[NS * F];
__device__ float2 Fc_g[F];
__device__ float2 Freq_g[NB * F];
__device__ float  Mol_g[NB * D];

__device__ __forceinline__ float2 cmulf(float2 a, float2 b) {
    return make_float2(a.x * b.x - a.y * b.y, a.x * b.y + a.y * b.x);
}

// DFT-5 constants: W5 = e^{-2pi i/5}
#define C51  0.30901699437494742f
#define S51  0.95105651629515357f
#define C52 (-0.80901699437494745f)
#define S52  0.58778525229247314f
// W10^t = (CT_t, -ST_t)
#define CT1  0.80901699437494742f
#define ST1  0.58778525229247314f
#define CT2  0.30901699437494742f
#define ST2  0.95105651629515357f

// ---------------- twiddle table build ----------------
__global__ void build_T_kernel() {
    int i = blockIdx.x * blockDim.x + threadIdx.x;
    if (i < 10000) {
        int j = i / 10, t = i % 10;
        float s, c;
        sincospif(-(float)(j * t) / 5000.0f, &s, &c);
        T_g[i] = make_float2(c, s);
    }
}

// ---------------- DFT-5 (Winograd-style, immediate constants) ----------
__device__ __forceinline__ void dft5(const float2* a, float2* A) {
    float2 t1 = make_float2(a[1].x + a[4].x, a[1].y + a[4].y);
    float2 t2 = make_float2(a[2].x + a[3].x, a[2].y + a[3].y);
    float2 t3 = make_float2(a[1].x - a[4].x, a[1].y - a[4].y);
    float2 t4 = make_float2(a[2].x - a[3].x, a[2].y - a[3].y);
    A[0] = make_float2(a[0].x + t1.x + t2.x, a[0].y + t1.y + t2.y);
    float2 b1 = make_float2(a[0].x + C51 * t1.x + C52 * t2.x,
                            a[0].y + C51 * t1.y + C52 * t2.y);
    float2 b2 = make_float2(a[0].x + C52 * t1.x + C51 * t2.x,
                            a[0].y + C52 * t1.y + C51 * t2.y);
    float2 p  = make_float2(S51 * t3.x + S52 * t4.x, S51 * t3.y + S52 * t4.y);
    float2 q  = make_float2(S52 * t3.x - S51 * t4.x, S52 * t3.y - S51 * t4.y);
    A[1] = make_float2(b1.x + p.y, b1.y - p.x);
    A[4] = make_float2(b1.x - p.y, b1.y + p.x);
    A[2] = make_float2(b2.x + q.y, b2.y - q.x);
    A[3] = make_float2(b2.x - q.y, b2.y + q.x);
}

// ---------------- radix-10 Stockham core (N=10000, 4 stages) -----------
// result ends back in bufA, synced. 1 butterfly per thread (tid < 1000).
__device__ void fft_core(float2* bufA, float2* bufB) {
    float2* src = bufA;
    float2* dst = bufB;
    int m = 1, step = 1;
#pragma unroll
    for (int stage = 0; stage < 4; stage++) {
        int bf = threadIdx.x;
        if (bf < 1000) {
            int j = bf / m;
            int k = bf - j * m;
            float2 u[10];
#pragma unroll
            for (int q = 0; q < 10; q++) u[q] = src[SK(bf + q * 1000)];

            // DFT-10 = 2 x DFT-5 + radix-2 combine
            float2 E[5], O[5];
            {
                float2 a[5];
#pragma unroll
                for (int r = 0; r < 5; r++) a[r] = u[2 * r];
                dft5(a, E);
#pragma unroll
                for (int r = 0; r < 5; r++) a[r] = u[2 * r + 1];
                dft5(a, O);
            }
            float2 v[10];
            {
                float2 wo;
                v[0] = make_float2(E[0].x + O[0].x, E[0].y + O[0].y);
                v[5] = make_float2(E[0].x - O[0].x, E[0].y - O[0].y);
                wo = cmulf(O[1], make_float2(CT1, -ST1));
                v[1] = make_float2(E[1].x + wo.x, E[1].y + wo.y);
                v[6] = make_float2(E[1].x - wo.x, E[1].y - wo.y);
                wo = cmulf(O[2], make_float2(CT2, -ST2));
                v[2] = make_float2(E[2].x + wo.x, E[2].y + wo.y);
                v[7] = make_float2(E[2].x - wo.x, E[2].y - wo.y);
                wo = cmulf(O[3], make_float2(-CT2, -ST2));
                v[3] = make_float2(E[3].x + wo.x, E[3].y + wo.y);
                v[8] = make_float2(E[3].x - wo.x, E[3].y - wo.y);
                wo = cmulf(O[4], make_float2(-CT1, -ST1));
                v[4] = make_float2(E[4].x + wo.x, E[4].y + wo.y);
                v[9] = make_float2(E[4].x - wo.x, E[4].y - wo.y);
            }

            if (j != 0) {
                const float4* tp =
                    reinterpret_cast<const float4*>(T_g + (j * step) * 10);
                float4 r0 = tp[0], r1 = tp[1], r2 = tp[2], r3 = tp[3], r4 = tp[4];
                v[1] = cmulf(v[1], make_float2(r0.z, r0.w));
                v[2] = cmulf(v[2], make_float2(r1.x, r1.y));
                v[3] = cmulf(v[3], make_float2(r1.z, r1.w));
                v[4] = cmulf(v[4], make_float2(r2.x, r2.y));
                v[5] = cmulf(v[5], make_float2(r2.z, r2.w));
                v[6] = cmulf(v[6], make_float2(r3.x, r3.y));
                v[7] = cmulf(v[7], make_float2(r3.z, r3.w));
                v[8] = cmulf(v[8], make_float2(r4.x, r4.y));
                v[9] = cmulf(v[9], make_float2(r4.z, r4.w));
            }
            int ob = k + 10 * j * m;
#pragma unroll
            for (int t = 0; t < 10; t++) dst[SK(ob + t * m)] = v[t];
        }
        __syncthreads();
        float2* tmp = src; src = dst; dst = tmp;
        m *= 10; step *= 10;
    }
}

// ---------------- forward FFT (store Hermitian half) ----------------
__global__ void __launch_bounds__(FFTTHREADS, 1)
fwd_fft_kernel(const float* __restrict__ atom,
               const float* __restrict__ pos,
               const float* __restrict__ clos) {
    extern __shared__ float2 sb[];
    int v = blockIdx.x;
    const float* x;
    float2* out;
    if (v < NA)            { x = atom + v * D;        out = Fa_g + v * F; }
    else if (v < NA + NS)  { x = pos + (v - NA) * D;  out = Fp_g + (v - NA) * F; }
    else                   { x = clos;                out = Fc_g; }

    for (int i = threadIdx.x; i < D; i += blockDim.x)
        sb[SK(i)] = make_float2(x[i], 0.f);
    __syncthreads();
    fft_core(sb, sb + SBUF);
    for (int i = threadIdx.x; i < F; i += blockDim.x)
        out[i] = sb[SK(i)];
}

// ---------------- frequency combine (bins 0..5000) ----------------
__global__ void combine_kernel(const float* __restrict__ tmask,
                               const float* __restrict__ rmask,
                               const int*   __restrict__ aidx,
                               const int*   __restrict__ rpos) {
    __shared__ int   s_idx[BG][NS];
    __shared__ float s_m[BG][NS];
    __shared__ int   s_rp[BG][NR][2];
    __shared__ float s_rm[BG][NR];
    __shared__ float2 s_fa[NA][128];

    int b0 = blockIdx.y * BG;
    int tx = threadIdx.x;

    for (int t = tx; t < BG * NS; t += 128) {
        int bb = t / NS, s = t % NS;
        s_idx[bb][s] = aidx[(b0 + bb) * NS + s];
        s_m[bb][s]   = tmask[(b0 + bb) * NS + s];
    }
    for (int t = tx; t < BG * NR; t += 128) {
        int bb = t / NR, r = t % NR;
        s_rp[bb][r][0] = rpos[((b0 + bb) * NR + r) * 2 + 0];
        s_rp[bb][r][1] = rpos[((b0 + bb) * NR + r) * 2 + 1];
        s_rm[bb][r]    = rmask[(b0 + bb) * NR + r];
    }
    int f = blockIdx.x * 128 + tx;
    if (f < F) {
        for (int i = 0; i < NA; i++) s_fa[i][tx] = Fa_g[i * F + f];
    }
    __syncthreads();
    if (f >= F) return;

    float2 fc = Fc_g[f];
    float2 acc[BG];
#pragma unroll
    for (int bb = 0; bb < BG; bb++) acc[bb] = make_float2(0.f, 0.f);

    for (int s = 0; s < NS; s++) {
        float2 fp = Fp_g[s * F + f];
#pragma unroll
        for (int bb = 0; bb < BG; bb++) {
            int   a  = s_idx[bb][s];
            float mm = s_m[bb][s];
            float2 fa = s_fa[a][tx];
            acc[bb].x += mm * (fa.x * fp.x - fa.y * fp.y);
            acc[bb].y += mm * (fa.x * fp.y + fa.y * fp.x);
        }
    }
#pragma unroll
    for (int bb = 0; bb < BG; bb++) {
        for (int r = 0; r < NR; r++) {
            float2 f0 = Fp_g[s_rp[bb][r][0] * F + f];
            float2 f1 = Fp_g[s_rp[bb][r][1] * F + f];
            float2 t  = cmulf(cmulf(f0, f1), fc);
            float mm  = s_rm[bb][r];
            acc[bb].x += mm * t.x;
            acc[bb].y += mm * t.y;
        }
    }
#pragma unroll
    for (int bb = 0; bb < BG; bb++)
        Freq_g[(b0 + bb) * F + f] = acc[bb];
}

// ---------------- inverse FFT (Hermitian reconstruct + conj trick) -----
__global__ void __launch_bounds__(FFTTHREADS, 1)
inv_fft_kernel() {
    extern __shared__ float2 sb[];
    int b = blockIdx.x;
    const float2* in = Freq_g + b * F;
    for (int i = threadIdx.x; i < D; i += blockDim.x) {
        float2 z;
        if (i < F) { z = in[i]; z.y = -z.y; }
        else       { z = in[D - i]; }
        sb[SK(i)] = z;
    }
    __syncthreads();
    fft_core(sb, sb + SBUF);
    const float inv = 1.0f / (float)D;
    for (int i = threadIdx.x; i < D; i += blockDim.x)
        Mol_g[b * D + i] = sb[SK(i)].x * inv;
}

// ---------------- projection ----------------
__global__ void init_out_kernel(const float* __restrict__ bias,
                                float* __restrict__ out) {
    int b = blockIdx.x, p = threadIdx.x;
    out[b * NP + p] = bias[p];
}

__global__ void __launch_bounds__(256)
proj_kernel(const float* __restrict__ Wm, float* __restrict__ out) {
    __shared__ float sA[64][DLEN + 1];
    __shared__ float sW[64][DLEN + 1];
    int pb = blockIdx.x;
    int ds = blockIdx.y;
    int dbase = ds * DLEN;
    int tid = threadIdx.x;

    for (int t = tid; t < 64 * DLEN; t += 256) {
        int r = t / DLEN, dd = t - r * DLEN;
        sA[r][dd] = Mol_g[r * D + dbase + dd];
    }
    for (int t = tid; t < 64 * DLEN; t += 256) {
        int r = t / DLEN, dd = t - r * DLEN;
        sW[r][dd] = Wm[(pb * 64 + r) * D + dbase + dd];
    }
    __syncthreads();

    int tx = tid & 15;
    int ty = tid >> 4;
    float acc[4][4];
#pragma unroll
    for (int i = 0; i < 4; i++)
#pragma unroll
        for (int j = 0; j < 4; j++) acc[i][j] = 0.f;

#pragma unroll 8
    for (int dd = 0; dd < DLEN; dd++) {
        float a0 = sA[ty * 4 + 0][dd];
        float a1 = sA[ty * 4 + 1][dd];
        float a2 = sA[ty * 4 + 2][dd];
        float a3 = sA[ty * 4 + 3][dd];
        float w0 = sW[tx * 4 + 0][dd];
        float w1 = sW[tx * 4 + 1][dd];
        float w2 = sW[tx * 4 + 2][dd];
        float w3 = sW[tx * 4 + 3][dd];
        acc[0][0] += a0 * w0; acc[0][1] += a0 * w1; acc[0][2] += a0 * w2; acc[0][3] += a0 * w3;
        acc[1][0] += a1 * w0; acc[1][1] += a1 * w1; acc[1][2] += a1 * w2; acc[1][3] += a1 * w3;
        acc[2][0] += a2 * w0; acc[2][1] += a2 * w1; acc[2][2] += a2 * w2; acc[2][3] += a2 * w3;
        acc[3][0] += a3 * w0; acc[3][1] += a3 * w1; acc[3][2] += a3 * w2; acc[3][3] += a3 * w3;
    }
#pragma unroll
    for (int i = 0; i < 4; i++) {
        int b = ty * 4 + i;
#pragma unroll
        for (int j = 0; j < 4; j++) {
            int p = pb * 64 + tx * 4 + j;
            atomicAdd(&out[b * NP + p], acc[i][j]);
        }
    }
}

// ---------------- launch ----------------
extern "C" void kernel_launch(void* const* d_in, const int* in_sizes, int n_in,
                              void* d_out, int out_size) {
    const float* atom  = (const float*)d_in[0];
    const float* pos   = (const float*)d_in[1];
    const float* clos  = (const float*)d_in[2];
    const float* Wm    = (const float*)d_in[3];
    const float* bias  = (const float*)d_in[4];
    const float* tmask = (const float*)d_in[5];
    const float* rmask = (const float*)d_in[6];
    const int*   aidx  = (const int*)d_in[7];
    const int*   rpos  = (const int*)d_in[8];
    float* out = (float*)d_out;

    size_t smem = 2 * (size_t)SBUF * sizeof(float2);   // 169984 B
    cudaFuncSetAttribute(fwd_fft_kernel,
                         cudaFuncAttributeMaxDynamicSharedMemorySize, (int)smem);
    cudaFuncSetAttribute(inv_fft_kernel,
                         cudaFuncAttributeMaxDynamicSharedMemorySize, (int)smem);

    build_T_kernel<<<(10000 + 255) / 256, 256>>>();
    fwd_fft_kernel<<<NA + NS + 1, FFTTHREADS, smem>>>(atom, pos, clos);

    dim3 cg((F + 127) / 128, NB / BG);
    combine_kernel<<<cg, 128>>>(tmask, rmask, aidx, rpos);

    inv_fft_kernel<<<NB, FFTTHREADS, smem>>>();

    init_out_kernel<<<NB, NP>>>(bias, out);
    dim3 pg(NP / 64, DSPLIT);
    proj_kernel<<<pg, 256>>>(Wm, out);
}

// round 5
// speedup vs baseline: 1.2354x; 1.2354x over previous
#include <cuda_runtime.h>
#include <stdint.h>

#define D     10000
#define F     5001      // Hermitian bins 0..5000
#define NB    64
#define NS    128
#define NA    10
#define NR    8
#define NP    256
#define FFTTHREADS 1024
#define BG    8

// proj tiling
#define DSPLIT 125
#define DLEN   80       // D / DSPLIT

// skewed smem index: pad every 16 float2 (128B) to break conflicts
#define SK(i) ((i) + ((i) >> 4))
#define SBUF  10624      // SK(9999)+1

// ---------------- device scratch ----------------
__device__ float2 T_g[1000 * 10];     // T[j][t] = exp(-2*pi*i*j*t/D)
__device__ float2 Fa_g[NA * F];
__device__ float2 Fp_g[NS * F];
__device__ float2 Fc_g[F];
__device__ float2 Freq_g[NB * F];
__device__ float  Mol_g[NB * D];

__device__ __forceinline__ float2 cmulf(float2 a, float2 b) {
    return make_float2(a.x * b.x - a.y * b.y, a.x * b.y + a.y * b.x);
}

// DFT-5 constants: W5 = e^{-2pi i/5}
#define C51  0.30901699437494742f
#define S51  0.95105651629515357f
#define C52 (-0.80901699437494745f)
#define S52  0.58778525229247314f
// W10^t = (CT_t, -ST_t)
#define CT1  0.80901699437494742f
#define ST1  0.58778525229247314f
#define CT2  0.30901699437494742f
#define ST2  0.95105651629515357f

// ---------------- twiddle table build ----------------
__global__ void build_T_kernel() {
    int i = blockIdx.x * blockDim.x + threadIdx.x;
    if (i < 10000) {
        int j = i / 10, t = i % 10;
        float s, c;
        sincospif(-(float)(j * t) / 5000.0f, &s, &c);
        T_g[i] = make_float2(c, s);
    }
}

// ---------------- DFT-5 (Winograd-style, immediate constants) ----------
__device__ __forceinline__ void dft5(const float2* a, float2* A) {
    float2 t1 = make_float2(a[1].x + a[4].x, a[1].y + a[4].y);
    float2 t2 = make_float2(a[2].x + a[3].x, a[2].y + a[3].y);
    float2 t3 = make_float2(a[1].x - a[4].x, a[1].y - a[4].y);
    float2 t4 = make_float2(a[2].x - a[3].x, a[2].y - a[3].y);
    A[0] = make_float2(a[0].x + t1.x + t2.x, a[0].y + t1.y + t2.y);
    float2 b1 = make_float2(a[0].x + C51 * t1.x + C52 * t2.x,
                            a[0].y + C51 * t1.y + C52 * t2.y);
    float2 b2 = make_float2(a[0].x + C52 * t1.x + C51 * t2.x,
                            a[0].y + C52 * t1.y + C51 * t2.y);
    float2 p  = make_float2(S51 * t3.x + S52 * t4.x, S51 * t3.y + S52 * t4.y);
    float2 q  = make_float2(S52 * t3.x - S51 * t4.x, S52 * t3.y - S51 * t4.y);
    A[1] = make_float2(b1.x + p.y, b1.y - p.x);
    A[4] = make_float2(b1.x - p.y, b1.y + p.x);
    A[2] = make_float2(b2.x + q.y, b2.y - q.x);
    A[3] = make_float2(b2.x - q.y, b2.y + q.x);
}

// ---------------- DFT-10 = 2 x DFT-5 + radix-2 combine ----------------
__device__ __forceinline__ void dft10(const float2* u, float2* v) {
    float2 E[5], O[5];
    {
        float2 a[5];
#pragma unroll
        for (int r = 0; r < 5; r++) a[r] = u[2 * r];
        dft5(a, E);
#pragma unroll
        for (int r = 0; r < 5; r++) a[r] = u[2 * r + 1];
        dft5(a, O);
    }
    float2 wo;
    v[0] = make_float2(E[0].x + O[0].x, E[0].y + O[0].y);
    v[5] = make_float2(E[0].x - O[0].x, E[0].y - O[0].y);
    wo = cmulf(O[1], make_float2(CT1, -ST1));
    v[1] = make_float2(E[1].x + wo.x, E[1].y + wo.y);
    v[6] = make_float2(E[1].x - wo.x, E[1].y - wo.y);
    wo = cmulf(O[2], make_float2(CT2, -ST2));
    v[2] = make_float2(E[2].x + wo.x, E[2].y + wo.y);
    v[7] = make_float2(E[2].x - wo.x, E[2].y - wo.y);
    wo = cmulf(O[3], make_float2(-CT2, -ST2));
    v[3] = make_float2(E[3].x + wo.x, E[3].y + wo.y);
    v[8] = make_float2(E[3].x - wo.x, E[3].y - wo.y);
    wo = cmulf(O[4], make_float2(-CT1, -ST1));
    v[4] = make_float2(E[4].x + wo.x, E[4].y + wo.y);
    v[9] = make_float2(E[4].x - wo.x, E[4].y - wo.y);
}

__device__ __forceinline__ void twiddle9(float2* v, int row) {
    const float4* tp = reinterpret_cast<const float4*>(T_g + row * 10);
    float4 r0 = tp[0], r1 = tp[1], r2 = tp[2], r3 = tp[3], r4 = tp[4];
    v[1] = cmulf(v[1], make_float2(r0.z, r0.w));
    v[2] = cmulf(v[2], make_float2(r1.x, r1.y));
    v[3] = cmulf(v[3], make_float2(r1.z, r1.w));
    v[4] = cmulf(v[4], make_float2(r2.x, r2.y));
    v[5] = cmulf(v[5], make_float2(r2.z, r2.w));
    v[6] = cmulf(v[6], make_float2(r3.x, r3.y));
    v[7] = cmulf(v[7], make_float2(r3.z, r3.w));
    v[8] = cmulf(v[8], make_float2(r4.x, r4.y));
    v[9] = cmulf(v[9], make_float2(r4.z, r4.w));
}

// ---------------- middle stages 1 & 2 (smem -> smem) ----------------
// entry: bufA holds stage-0 output; exit: bufA holds stage-2 output (synced)
__device__ __forceinline__ void fft_mid(float2* bufA, float2* bufB, int bf) {
    // stage 1: m=10, step=10
    if (bf < 1000) {
        int j = bf / 10, k = bf - j * 10;
        float2 u[10];
#pragma unroll
        for (int q = 0; q < 10; q++) u[q] = bufA[SK(bf + q * 1000)];
        float2 v[10];
        dft10(u, v);
        if (j) twiddle9(v, j * 10);
        int ob = k + 100 * j;
#pragma unroll
        for (int t = 0; t < 10; t++) bufB[SK(ob + 10 * t)] = v[t];
    }
    __syncthreads();
    // stage 2: m=100, step=100
    if (bf < 1000) {
        int j = bf / 100, k = bf - j * 100;
        float2 u[10];
#pragma unroll
        for (int q = 0; q < 10; q++) u[q] = bufB[SK(bf + q * 1000)];
        float2 v[10];
        dft10(u, v);
        if (j) twiddle9(v, j * 100);
        int ob = k + 1000 * j;
#pragma unroll
        for (int t = 0; t < 10; t++) bufA[SK(ob + 100 * t)] = v[t];
    }
    __syncthreads();
}

// ---------------- forward FFT (global in, Hermitian half out) ----------
__global__ void __launch_bounds__(FFTTHREADS, 1)
fwd_fft_kernel(const float* __restrict__ atom,
               const float* __restrict__ pos,
               const float* __restrict__ clos) {
    extern __shared__ float2 sb[];
    float2* bufA = sb;
    float2* bufB = sb + SBUF;
    int vb = blockIdx.x;
    const float* x;
    float2* out;
    if (vb < NA)           { x = atom + vb * D;        out = Fa_g + vb * F; }
    else if (vb < NA + NS) { x = pos + (vb - NA) * D;  out = Fp_g + (vb - NA) * F; }
    else                   { x = clos;                 out = Fc_g; }

    int bf = threadIdx.x;
    // stage 0 (m=1): read global directly; imag parts fold to 0
    if (bf < 1000) {
        float2 u[10];
#pragma unroll
        for (int q = 0; q < 10; q++) u[q] = make_float2(x[bf + q * 1000], 0.f);
        float2 v[10];
        dft10(u, v);
        if (bf) twiddle9(v, bf);
#pragma unroll
        for (int t = 0; t < 10; t++) bufA[SK(10 * bf + t)] = v[t];
    }
    __syncthreads();

    fft_mid(bufA, bufB, bf);

    // stage 3 (m=1000, j=0): write global directly, natural order
    if (bf < 1000) {
        float2 u[10];
#pragma unroll
        for (int q = 0; q < 10; q++) u[q] = bufA[SK(bf + q * 1000)];
        float2 v[10];
        dft10(u, v);
#pragma unroll
        for (int t = 0; t < 10; t++) {
            int p = bf + 1000 * t;
            if (p < F) out[p] = v[t];
        }
    }
}

// ---------------- frequency combine (bins 0..5000) ----------------
__global__ void combine_kernel(const float* __restrict__ tmask,
                               const float* __restrict__ rmask,
                               const int*   __restrict__ aidx,
                               const int*   __restrict__ rpos) {
    __shared__ int   s_idx[BG][NS];
    __shared__ float s_m[BG][NS];
    __shared__ int   s_rp[BG][NR][2];
    __shared__ float s_rm[BG][NR];
    __shared__ float2 s_fa[NA][128];

    int b0 = blockIdx.y * BG;
    int tx = threadIdx.x;

    for (int t = tx; t < BG * NS; t += 128) {
        int bb = t / NS, s = t % NS;
        s_idx[bb][s] = aidx[(b0 + bb) * NS + s];
        s_m[bb][s]   = tmask[(b0 + bb) * NS + s];
    }
    for (int t = tx; t < BG * NR; t += 128) {
        int bb = t / NR, r = t % NR;
        s_rp[bb][r][0] = rpos[((b0 + bb) * NR + r) * 2 + 0];
        s_rp[bb][r][1] = rpos[((b0 + bb) * NR + r) * 2 + 1];
        s_rm[bb][r]    = rmask[(b0 + bb) * NR + r];
    }
    int f = blockIdx.x * 128 + tx;
    if (f < F) {
        for (int i = 0; i < NA; i++) s_fa[i][tx] = Fa_g[i * F + f];
    }
    __syncthreads();
    if (f >= F) return;

    float2 fc = Fc_g[f];
    float2 acc[BG];
#pragma unroll
    for (int bb = 0; bb < BG; bb++) acc[bb] = make_float2(0.f, 0.f);

    for (int s = 0; s < NS; s++) {
        float2 fp = Fp_g[s * F + f];
#pragma unroll
        for (int bb = 0; bb < BG; bb++) {
            int   a  = s_idx[bb][s];
            float mm = s_m[bb][s];
            float2 fa = s_fa[a][tx];
            acc[bb].x += mm * (fa.x * fp.x - fa.y * fp.y);
            acc[bb].y += mm * (fa.x * fp.y + fa.y * fp.x);
        }
    }
#pragma unroll
    for (int bb = 0; bb < BG; bb++) {
        for (int r = 0; r < NR; r++) {
            float2 f0 = Fp_g[s_rp[bb][r][0] * F + f];
            float2 f1 = Fp_g[s_rp[bb][r][1] * F + f];
            float2 t  = cmulf(cmulf(f0, f1), fc);
            float mm  = s_rm[bb][r];
            acc[bb].x += mm * t.x;
            acc[bb].y += mm * t.y;
        }
    }
#pragma unroll
    for (int bb = 0; bb < BG; bb++)
        Freq_g[(b0 + bb) * F + f] = acc[bb];
}

// ---------------- inverse FFT (Hermitian reconstruct, conj trick) ------
__global__ void __launch_bounds__(FFTTHREADS, 1)
inv_fft_kernel() {
    extern __shared__ float2 sb[];
    float2* bufA = sb;
    float2* bufB = sb + SBUF;
    int b = blockIdx.x;
    const float2* in = Freq_g + b * F;

    int bf = threadIdx.x;
    // stage 0: reconstruct conj(full spectrum) straight from global
    if (bf < 1000) {
        float2 u[10];
#pragma unroll
        for (int q = 0; q < 10; q++) {
            int i = bf + q * 1000;
            float2 z;
            if (i < F) { z = in[i]; z.y = -z.y; }  // conj(X[i])
            else       { z = in[D - i]; }          // X[D-i] (already conj pair)
            u[q] = z;
        }
        float2 v[10];
        dft10(u, v);
        if (bf) twiddle9(v, bf);
#pragma unroll
        for (int t = 0; t < 10; t++) bufA[SK(10 * bf + t)] = v[t];
    }
    __syncthreads();

    fft_mid(bufA, bufB, bf);

    // stage 3: write real part to Mol directly
    if (bf < 1000) {
        float2 u[10];
#pragma unroll
        for (int q = 0; q < 10; q++) u[q] = bufA[SK(bf + q * 1000)];
        float2 v[10];
        dft10(u, v);
        const float inv = 1.0f / (float)D;
        float* mo = Mol_g + b * D;
#pragma unroll
        for (int t = 0; t < 10; t++) mo[bf + 1000 * t] = v[t].x * inv;
    }
}

// ---------------- projection ----------------
__global__ void init_out_kernel(const float* __restrict__ bias,
                                float* __restrict__ out) {
    int b = blockIdx.x, p = threadIdx.x;
    out[b * NP + p] = bias[p];
}

__global__ void __launch_bounds__(256)
proj_kernel(const float* __restrict__ Wm, float* __restrict__ out) {
    __shared__ float sA[64][DLEN + 1];
    __shared__ float sW[64][DLEN + 1];
    int pb = blockIdx.x;
    int ds = blockIdx.y;
    int dbase = ds * DLEN;
    int tid = threadIdx.x;

    for (int t = tid; t < 64 * DLEN; t += 256) {
        int r = t / DLEN, dd = t - r * DLEN;
        sA[r][dd] = Mol_g[r * D + dbase + dd];
    }
    for (int t = tid; t < 64 * DLEN; t += 256) {
        int r = t / DLEN, dd = t - r * DLEN;
        sW[r][dd] = Wm[(pb * 64 + r) * D + dbase + dd];
    }
    __syncthreads();

    int tx = tid & 15;
    int ty = tid >> 4;
    float acc[4][4];
#pragma unroll
    for (int i = 0; i < 4; i++)
#pragma unroll
        for (int j = 0; j < 4; j++) acc[i][j] = 0.f;

#pragma unroll 8
    for (int dd = 0; dd < DLEN; dd++) {
        float a0 = sA[ty * 4 + 0][dd];
        float a1 = sA[ty * 4 + 1][dd];
        float a2 = sA[ty * 4 + 2][dd];
        float a3 = sA[ty * 4 + 3][dd];
        float w0 = sW[tx * 4 + 0][dd];
        float w1 = sW[tx * 4 + 1][dd];
        float w2 = sW[tx * 4 + 2][dd];
        float w3 = sW[tx * 4 + 3][dd];
        acc[0][0] += a0 * w0; acc[0][1] += a0 * w1; acc[0][2] += a0 * w2; acc[0][3] += a0 * w3;
        acc[1][0] += a1 * w0; acc[1][1] += a1 * w1; acc[1][2] += a1 * w2; acc[1][3] += a1 * w3;
        acc[2][0] += a2 * w0; acc[2][1] += a2 * w1; acc[2][2] += a2 * w2; acc[2][3] += a2 * w3;
        acc[3][0] += a3 * w0; acc[3][1] += a3 * w1; acc[3][2] += a3 * w2; acc[3][3] += a3 * w3;
    }
#pragma unroll
    for (int i = 0; i < 4; i++) {
        int b = ty * 4 + i;
#pragma unroll
        for (int j = 0; j < 4; j++) {
            int p = pb * 64 + tx * 4 + j;
            atomicAdd(&out[b * NP + p], acc[i][j]);
        }
    }
}

// ---------------- launch ----------------
extern "C" void kernel_launch(void* const* d_in, const int* in_sizes, int n_in,
                              void* d_out, int out_size) {
    const float* atom  = (const float*)d_in[0];
    const float* pos   = (const float*)d_in[1];
    const float* clos  = (const float*)d_in[2];
    const float* Wm    = (const float*)d_in[3];
    const float* bias  = (const float*)d_in[4];
    const float* tmask = (const float*)d_in[5];
    const float* rmask = (const float*)d_in[6];
    const int*   aidx  = (const int*)d_in[7];
    const int*   rpos  = (const int*)d_in[8];
    float* out = (float*)d_out;

    size_t smem = 2 * (size_t)SBUF * sizeof(float2);   // 169984 B
    cudaFuncSetAttribute(fwd_fft_kernel,
                         cudaFuncAttributeMaxDynamicSharedMemorySize, (int)smem);
    cudaFuncSetAttribute(inv_fft_kernel,
                         cudaFuncAttributeMaxDynamicSharedMemorySize, (int)smem);

    build_T_kernel<<<(10000 + 255) / 256, 256>>>();
    fwd_fft_kernel<<<NA + NS + 1, FFTTHREADS, smem>>>(atom, pos, clos);

    dim3 cg((F + 127) / 128, NB / BG);
    combine_kernel<<<cg, 128>>>(tmask, rmask, aidx, rpos);

    inv_fft_kernel<<<NB, FFTTHREADS, smem>>>();

    init_out_kernel<<<NB, NP>>>(bias, out);
    dim3 pg(NP / 64, DSPLIT);
    proj_kernel<<<pg, 256>>>(Wm, out);
}

// round 6
// speedup vs baseline: 1.4232x; 1.1520x over previous
#include <cuda_runtime.h>
#include <stdint.h>

#define D     10000
#define F     5001      // Hermitian bins 0..5000
#define NB    64
#define NS    128
#define NA    10
#define NR    8
#define NP    256
#define FFTTHREADS 1024
#define BG    8

// proj tiling
#define DSPLIT 125
#define DLEN   80       // D / DSPLIT

// conflict-free skew: pad 3 float2 per decade.
// stage-0 store stride becomes 13 (odd*2=26, gcd(26,32)=2 -> conflict-free 8B),
// loads stay near-contiguous, stage-1/2 stores <=2-way.
__device__ __forceinline__ int SKF(int i) { return i + 3 * (i / 10); }
#define SBUF  13000      // SKF(9999)+1 = 12997, rounded

// ---------------- device scratch ----------------
__device__ float2 T_g[1000 * 10];     // T[j][t] = exp(-2*pi*i*j*t/D)
__device__ float2 Fa_g[NA * F];
__device__ float2 Fp_g[NS * F];
__device__ float2 Fc_g[F];
__device__ float2 Freq_g[NB * F];
__device__ float  Mol_g[NB * D];

__device__ __forceinline__ float2 cmulf(float2 a, float2 b) {
    return make_float2(a.x * b.x - a.y * b.y, a.x * b.y + a.y * b.x);
}

// DFT-5 constants: W5 = e^{-2pi i/5}
#define C51  0.30901699437494742f
#define S51  0.95105651629515357f
#define C52 (-0.80901699437494745f)
#define S52  0.58778525229247314f
// W10^t = (CT_t, -ST_t)
#define CT1  0.80901699437494742f
#define ST1  0.58778525229247314f
#define CT2  0.30901699437494742f
#define ST2  0.95105651629515357f

// ---------------- twiddle table build ----------------
__global__ void build_T_kernel() {
    int i = blockIdx.x * blockDim.x + threadIdx.x;
    if (i < 10000) {
        int j = i / 10, t = i % 10;
        float s, c;
        sincospif(-(float)(j * t) / 5000.0f, &s, &c);
        T_g[i] = make_float2(c, s);
    }
}

// ---------------- DFT-5 (Winograd-style, immediate constants) ----------
__device__ __forceinline__ void dft5(const float2* a, float2* A) {
    float2 t1 = make_float2(a[1].x + a[4].x, a[1].y + a[4].y);
    float2 t2 = make_float2(a[2].x + a[3].x, a[2].y + a[3].y);
    float2 t3 = make_float2(a[1].x - a[4].x, a[1].y - a[4].y);
    float2 t4 = make_float2(a[2].x - a[3].x, a[2].y - a[3].y);
    A[0] = make_float2(a[0].x + t1.x + t2.x, a[0].y + t1.y + t2.y);
    float2 b1 = make_float2(a[0].x + C51 * t1.x + C52 * t2.x,
                            a[0].y + C51 * t1.y + C52 * t2.y);
    float2 b2 = make_float2(a[0].x + C52 * t1.x + C51 * t2.x,
                            a[0].y + C52 * t1.y + C51 * t2.y);
    float2 p  = make_float2(S51 * t3.x + S52 * t4.x, S51 * t3.y + S52 * t4.y);
    float2 q  = make_float2(S52 * t3.x - S51 * t4.x, S52 * t3.y - S51 * t4.y);
    A[1] = make_float2(b1.x + p.y, b1.y - p.x);
    A[4] = make_float2(b1.x - p.y, b1.y + p.x);
    A[2] = make_float2(b2.x + q.y, b2.y - q.x);
    A[3] = make_float2(b2.x - q.y, b2.y + q.x);
}

// ---------------- DFT-10 = 2 x DFT-5 + radix-2 combine ----------------
__device__ __forceinline__ void dft10(const float2* u, float2* v) {
    float2 E[5], O[5];
    {
        float2 a[5];
#pragma unroll
        for (int r = 0; r < 5; r++) a[r] = u[2 * r];
        dft5(a, E);
#pragma unroll
        for (int r = 0; r < 5; r++) a[r] = u[2 * r + 1];
        dft5(a, O);
    }
    float2 wo;
    v[0] = make_float2(E[0].x + O[0].x, E[0].y + O[0].y);
    v[5] = make_float2(E[0].x - O[0].x, E[0].y - O[0].y);
    wo = cmulf(O[1], make_float2(CT1, -ST1));
    v[1] = make_float2(E[1].x + wo.x, E[1].y + wo.y);
    v[6] = make_float2(E[1].x - wo.x, E[1].y - wo.y);
    wo = cmulf(O[2], make_float2(CT2, -ST2));
    v[2] = make_float2(E[2].x + wo.x, E[2].y + wo.y);
    v[7] = make_float2(E[2].x - wo.x, E[2].y - wo.y);
    wo = cmulf(O[3], make_float2(-CT2, -ST2));
    v[3] = make_float2(E[3].x + wo.x, E[3].y + wo.y);
    v[8] = make_float2(E[3].x - wo.x, E[3].y - wo.y);
    wo = cmulf(O[4], make_float2(-CT1, -ST1));
    v[4] = make_float2(E[4].x + wo.x, E[4].y + wo.y);
    v[9] = make_float2(E[4].x - wo.x, E[4].y - wo.y);
}

__device__ __forceinline__ void twiddle9(float2* v, int row) {
    const float4* tp = reinterpret_cast<const float4*>(T_g + row * 10);
    float4 r0 = tp[0], r1 = tp[1], r2 = tp[2], r3 = tp[3], r4 = tp[4];
    v[1] = cmulf(v[1], make_float2(r0.z, r0.w));
    v[2] = cmulf(v[2], make_float2(r1.x, r1.y));
    v[3] = cmulf(v[3], make_float2(r1.z, r1.w));
    v[4] = cmulf(v[4], make_float2(r2.x, r2.y));
    v[5] = cmulf(v[5], make_float2(r2.z, r2.w));
    v[6] = cmulf(v[6], make_float2(r3.x, r3.y));
    v[7] = cmulf(v[7], make_float2(r3.z, r3.w));
    v[8] = cmulf(v[8], make_float2(r4.x, r4.y));
    v[9] = cmulf(v[9], make_float2(r4.z, r4.w));
}

// ---------------- middle stages 1 & 2 (smem -> smem) ----------------
__device__ __forceinline__ void fft_mid(float2* bufA, float2* bufB, int bf) {
    // stage 1: m=10, step=10
    if (bf < 1000) {
        int j = bf / 10, k = bf - j * 10;
        float2 u[10];
#pragma unroll
        for (int q = 0; q < 10; q++) u[q] = bufA[SKF(bf + q * 1000)];
        float2 v[10];
        dft10(u, v);
        if (j) twiddle9(v, j * 10);
        int ob = k + 100 * j;
#pragma unroll
        for (int t = 0; t < 10; t++) bufB[SKF(ob + 10 * t)] = v[t];
    }
    __syncthreads();
    // stage 2: m=100, step=100
    if (bf < 1000) {
        int j = bf / 100, k = bf - j * 100;
        float2 u[10];
#pragma unroll
        for (int q = 0; q < 10; q++) u[q] = bufB[SKF(bf + q * 1000)];
        float2 v[10];
        dft10(u, v);
        if (j) twiddle9(v, j * 100);
        int ob = k + 1000 * j;
#pragma unroll
        for (int t = 0; t < 10; t++) bufA[SKF(ob + 100 * t)] = v[t];
    }
    __syncthreads();
}

// ---------------- forward FFT (global in, Hermitian half out) ----------
__global__ void __launch_bounds__(FFTTHREADS, 1)
fwd_fft_kernel(const float* __restrict__ atom,
               const float* __restrict__ pos,
               const float* __restrict__ clos) {
    extern __shared__ float2 sb[];
    float2* bufA = sb;
    float2* bufB = sb + SBUF;
    int vb = blockIdx.x;
    const float* x;
    float2* out;
    if (vb < NA)           { x = atom + vb * D;        out = Fa_g + vb * F; }
    else if (vb < NA + NS) { x = pos + (vb - NA) * D;  out = Fp_g + (vb - NA) * F; }
    else                   { x = clos;                 out = Fc_g; }

    int bf = threadIdx.x;
    // stage 0 (m=1): read global directly; imag parts fold to 0
    if (bf < 1000) {
        float2 u[10];
#pragma unroll
        for (int q = 0; q < 10; q++) u[q] = make_float2(x[bf + q * 1000], 0.f);
        float2 v[10];
        dft10(u, v);
        if (bf) twiddle9(v, bf);
#pragma unroll
        for (int t = 0; t < 10; t++) bufA[13 * bf + t] = v[t];   // SKF(10bf+t)
    }
    __syncthreads();

    fft_mid(bufA, bufB, bf);

    // stage 3 (m=1000, j=0): write global directly, natural order
    if (bf < 1000) {
        float2 u[10];
#pragma unroll
        for (int q = 0; q < 10; q++) u[q] = bufA[SKF(bf + q * 1000)];
        float2 v[10];
        dft10(u, v);
#pragma unroll
        for (int t = 0; t < 10; t++) {
            int p = bf + 1000 * t;
            if (p < F) out[p] = v[t];
        }
    }
}

// ---------------- frequency combine (bins 0..5000) ----------------
__global__ void combine_kernel(const float* __restrict__ tmask,
                               const float* __restrict__ rmask,
                               const int*   __restrict__ aidx,
                               const int*   __restrict__ rpos) {
    __shared__ float2 s_mi[BG][NS];     // (mask, bitcast idx) fused
    __shared__ int   s_rp[BG][NR][2];
    __shared__ float s_rm[BG][NR];
    __shared__ float2 s_fa[NA][128];

    int b0 = blockIdx.y * BG;
    int tx = threadIdx.x;

    for (int t = tx; t < BG * NS; t += 128) {
        int bb = t / NS, s = t % NS;
        s_mi[bb][s] = make_float2(tmask[(b0 + bb) * NS + s],
                                  __int_as_float(aidx[(b0 + bb) * NS + s]));
    }
    for (int t = tx; t < BG * NR; t += 128) {
        int bb = t / NR, r = t % NR;
        s_rp[bb][r][0] = rpos[((b0 + bb) * NR + r) * 2 + 0];
        s_rp[bb][r][1] = rpos[((b0 + bb) * NR + r) * 2 + 1];
        s_rm[bb][r]    = rmask[(b0 + bb) * NR + r];
    }
    int f = blockIdx.x * 128 + tx;
    if (f < F) {
        for (int i = 0; i < NA; i++) s_fa[i][tx] = Fa_g[i * F + f];
    }
    __syncthreads();
    if (f >= F) return;

    float2 fc = Fc_g[f];
    float2 acc[BG];
#pragma unroll
    for (int bb = 0; bb < BG; bb++) acc[bb] = make_float2(0.f, 0.f);

#pragma unroll 4
    for (int s = 0; s < NS; s++) {
        float2 fp = Fp_g[s * F + f];
        float nfpy = -fp.y;
#pragma unroll
        for (int bb = 0; bb < BG; bb++) {
            float2 mi = s_mi[bb][s];
            int    a  = __float_as_int(mi.y);
            float2 fa = s_fa[a][tx];
            float p = mi.x * fa.x;
            float q = mi.x * fa.y;
            acc[bb].x += p * fp.x;
            acc[bb].x += q * nfpy;
            acc[bb].y += p * fp.y;
            acc[bb].y += q * fp.x;
        }
    }
#pragma unroll
    for (int bb = 0; bb < BG; bb++) {
        for (int r = 0; r < NR; r++) {
            float2 f0 = Fp_g[s_rp[bb][r][0] * F + f];
            float2 f1 = Fp_g[s_rp[bb][r][1] * F + f];
            float2 t  = cmulf(cmulf(f0, f1), fc);
            float mm  = s_rm[bb][r];
            acc[bb].x += mm * t.x;
            acc[bb].y += mm * t.y;
        }
    }
#pragma unroll
    for (int bb = 0; bb < BG; bb++)
        Freq_g[(b0 + bb) * F + f] = acc[bb];
}

// ---------------- inverse FFT (Hermitian reconstruct, conj trick) ------
__global__ void __launch_bounds__(FFTTHREADS, 1)
inv_fft_kernel() {
    extern __shared__ float2 sb[];
    float2* bufA = sb;
    float2* bufB = sb + SBUF;
    int b = blockIdx.x;
    const float2* in = Freq_g + b * F;

    int bf = threadIdx.x;
    if (bf < 1000) {
        float2 u[10];
#pragma unroll
        for (int q = 0; q < 10; q++) {
            int i = bf + q * 1000;
            float2 z;
            if (i < F) { z = in[i]; z.y = -z.y; }  // conj(X[i])
            else       { z = in[D - i]; }          // X[D-i] (conj pair)
            u[q] = z;
        }
        float2 v[10];
        dft10(u, v);
        if (bf) twiddle9(v, bf);
#pragma unroll
        for (int t = 0; t < 10; t++) bufA[13 * bf + t] = v[t];
    }
    __syncthreads();

    fft_mid(bufA, bufB, bf);

    if (bf < 1000) {
        float2 u[10];
#pragma unroll
        for (int q = 0; q < 10; q++) u[q] = bufA[SKF(bf + q * 1000)];
        float2 v[10];
        dft10(u, v);
        const float inv = 1.0f / (float)D;
        float* mo = Mol_g + b * D;
#pragma unroll
        for (int t = 0; t < 10; t++) mo[bf + 1000 * t] = v[t].x * inv;
    }
}

// ---------------- projection ----------------
__global__ void init_out_kernel(const float* __restrict__ bias,
                                float* __restrict__ out) {
    int b = blockIdx.x, p = threadIdx.x;
    out[b * NP + p] = bias[p];
}

__global__ void __launch_bounds__(256)
proj_kernel(const float* __restrict__ Wm, float* __restrict__ out) {
    __shared__ float sA[64][DLEN + 1];
    __shared__ float sW[64][DLEN + 1];
    int pb = blockIdx.x;
    int ds = blockIdx.y;
    int dbase = ds * DLEN;
    int tid = threadIdx.x;

    for (int t = tid; t < 64 * DLEN; t += 256) {
        int r = t / DLEN, dd = t - r * DLEN;
        sA[r][dd] = Mol_g[r * D + dbase + dd];
    }
    for (int t = tid; t < 64 * DLEN; t += 256) {
        int r = t / DLEN, dd = t - r * DLEN;
        sW[r][dd] = Wm[(pb * 64 + r) * D + dbase + dd];
    }
    __syncthreads();

    int tx = tid & 15;
    int ty = tid >> 4;
    float acc[4][4];
#pragma unroll
    for (int i = 0; i < 4; i++)
#pragma unroll
        for (int j = 0; j < 4; j++) acc[i][j] = 0.f;

#pragma unroll 8
    for (int dd = 0; dd < DLEN; dd++) {
        float a0 = sA[ty * 4 + 0][dd];
        float a1 = sA[ty * 4 + 1][dd];
        float a2 = sA[ty * 4 + 2][dd];
        float a3 = sA[ty * 4 + 3][dd];
        float w0 = sW[tx * 4 + 0][dd];
        float w1 = sW[tx * 4 + 1][dd];
        float w2 = sW[tx * 4 + 2][dd];
        float w3 = sW[tx * 4 + 3][dd];
        acc[0][0] += a0 * w0; acc[0][1] += a0 * w1; acc[0][2] += a0 * w2; acc[0][3] += a0 * w3;
        acc[1][0] += a1 * w0; acc[1][1] += a1 * w1; acc[1][2] += a1 * w2; acc[1][3] += a1 * w3;
        acc[2][0] += a2 * w0; acc[2][1] += a2 * w1; acc[2][2] += a2 * w2; acc[2][3] += a2 * w3;
        acc[3][0] += a3 * w0; acc[3][1] += a3 * w1; acc[3][2] += a3 * w2; acc[3][3] += a3 * w3;
    }
#pragma unroll
    for (int i = 0; i < 4; i++) {
        int b = ty * 4 + i;
#pragma unroll
        for (int j = 0; j < 4; j++) {
            int p = pb * 64 + tx * 4 + j;
            atomicAdd(&out[b * NP + p], acc[i][j]);
        }
    }
}

// ---------------- launch ----------------
extern "C" void kernel_launch(void* const* d_in, const int* in_sizes, int n_in,
                              void* d_out, int out_size) {
    const float* atom  = (const float*)d_in[0];
    const float* pos   = (const float*)d_in[1];
    const float* clos  = (const float*)d_in[2];
    const float* Wm    = (const float*)d_in[3];
    const float* bias  = (const float*)d_in[4];
    const float* tmask = (const float*)d_in[5];
    const float* rmask = (const float*)d_in[6];
    const int*   aidx  = (const int*)d_in[7];
    const int*   rpos  = (const int*)d_in[8];
    float* out = (float*)d_out;

    size_t smem = 2 * (size_t)SBUF * sizeof(float2);   // 208000 B
    cudaFuncSetAttribute(fwd_fft_kernel,
                         cudaFuncAttributeMaxDynamicSharedMemorySize, (int)smem);
    cudaFuncSetAttribute(inv_fft_kernel,
                         cudaFuncAttributeMaxDynamicSharedMemorySize, (int)smem);

    build_T_kernel<<<(10000 + 255) / 256, 256>>>();
    fwd_fft_kernel<<<NA + NS + 1, FFTTHREADS, smem>>>(atom, pos, clos);

    dim3 cg((F + 127) / 128, NB / BG);
    combine_kernel<<<cg, 128>>>(tmask, rmask, aidx, rpos);

    inv_fft_kernel<<<NB, FFTTHREADS, smem>>>();

    init_out_kernel<<<NB, NP>>>(bias, out);
    dim3 pg(NP / 64, DSPLIT);
    proj_kernel<<<pg, 256>>>(Wm, out);
}

// round 7
// speedup vs baseline: 1.5476x; 1.0874x over previous
#include <cuda_runtime.h>
#include <stdint.h>

#define D     10000
#define F     5001      // Hermitian bins 0..5000
#define NB    64
#define NS    128
#define NA    10
#define NR    8
#define NP    256
#define FFTTHREADS 1024
#define BG    8
#define SHALF 64        // s per combine z-slice

// proj tiling
#define DSPLIT 125
#define DLEN   80       // D / DSPLIT

// skew: pad 3 float2 per decade (stage-0 store stride 13)
__device__ __forceinline__ int SKF(int i) { return i + 3 * (i / 10); }
#define SBUF  13000

// ---------------- device scratch ----------------
__device__ float2 Fa_g[NA * F];
__device__ float2 Fp_g[NS * F];
__device__ float2 Fc_g[F];
__device__ float2 Freq_g[2][NB * F];   // two partial accumulators (z-split)
__device__ float  Mol_g[NB * D];

__device__ __forceinline__ float2 cmulf(float2 a, float2 b) {
    return make_float2(a.x * b.x - a.y * b.y, a.x * b.y + a.y * b.x);
}

// DFT-5 constants: W5 = e^{-2pi i/5}
#define C51  0.30901699437494742f
#define S51  0.95105651629515357f
#define C52 (-0.80901699437494745f)
#define S52  0.58778525229247314f
// W10^t = (CT_t, -ST_t)
#define CT1  0.80901699437494742f
#define ST1  0.58778525229247314f
#define CT2  0.30901699437494742f
#define ST2  0.95105651629515357f

// ---------------- DFT-5 (Winograd-style, immediate constants) ----------
__device__ __forceinline__ void dft5(const float2* a, float2* A) {
    float2 t1 = make_float2(a[1].x + a[4].x, a[1].y + a[4].y);
    float2 t2 = make_float2(a[2].x + a[3].x, a[2].y + a[3].y);
    float2 t3 = make_float2(a[1].x - a[4].x, a[1].y - a[4].y);
    float2 t4 = make_float2(a[2].x - a[3].x, a[2].y - a[3].y);
    A[0] = make_float2(a[0].x + t1.x + t2.x, a[0].y + t1.y + t2.y);
    float2 b1 = make_float2(a[0].x + C51 * t1.x + C52 * t2.x,
                            a[0].y + C51 * t1.y + C52 * t2.y);
    float2 b2 = make_float2(a[0].x + C52 * t1.x + C51 * t2.x,
                            a[0].y + C52 * t1.y + C51 * t2.y);
    float2 p  = make_float2(S51 * t3.x + S52 * t4.x, S51 * t3.y + S52 * t4.y);
    float2 q  = make_float2(S52 * t3.x - S51 * t4.x, S52 * t3.y - S51 * t4.y);
    A[1] = make_float2(b1.x + p.y, b1.y - p.x);
    A[4] = make_float2(b1.x - p.y, b1.y + p.x);
    A[2] = make_float2(b2.x + q.y, b2.y - q.x);
    A[3] = make_float2(b2.x - q.y, b2.y + q.x);
}

// ---------------- DFT-10 = 2 x DFT-5 + radix-2 combine ----------------
__device__ __forceinline__ void dft10(const float2* u, float2* v) {
    float2 E[5], O[5];
    {
        float2 a[5];
#pragma unroll
        for (int r = 0; r < 5; r++) a[r] = u[2 * r];
        dft5(a, E);
#pragma unroll
        for (int r = 0; r < 5; r++) a[r] = u[2 * r + 1];
        dft5(a, O);
    }
    float2 wo;
    v[0] = make_float2(E[0].x + O[0].x, E[0].y + O[0].y);
    v[5] = make_float2(E[0].x - O[0].x, E[0].y - O[0].y);
    wo = cmulf(O[1], make_float2(CT1, -ST1));
    v[1] = make_float2(E[1].x + wo.x, E[1].y + wo.y);
    v[6] = make_float2(E[1].x - wo.x, E[1].y - wo.y);
    wo = cmulf(O[2], make_float2(CT2, -ST2));
    v[2] = make_float2(E[2].x + wo.x, E[2].y + wo.y);
    v[7] = make_float2(E[2].x - wo.x, E[2].y - wo.y);
    wo = cmulf(O[3], make_float2(-CT2, -ST2));
    v[3] = make_float2(E[3].x + wo.x, E[3].y + wo.y);
    v[8] = make_float2(E[3].x - wo.x, E[3].y - wo.y);
    wo = cmulf(O[4], make_float2(-CT1, -ST1));
    v[4] = make_float2(E[4].x + wo.x, E[4].y + wo.y);
    v[9] = make_float2(E[4].x - wo.x, E[4].y - wo.y);
}

// ---------------- on-the-fly stage twiddles: W^(row*t), t=1..9 ----------
__device__ __forceinline__ void twiddle9_otf(float2* v, int row) {
    float s, c;
    sincospif((float)row * (-1.0f / 5000.0f), &s, &c);
    float2 w1 = make_float2(c, s);
    float2 w2 = cmulf(w1, w1);
    float2 w3 = cmulf(w2, w1);
    float2 w4 = cmulf(w2, w2);
    float2 w5 = cmulf(w4, w1);
    float2 w6 = cmulf(w4, w2);
    float2 w7 = cmulf(w4, w3);
    float2 w8 = cmulf(w4, w4);
    float2 w9 = cmulf(w8, w1);
    v[1] = cmulf(v[1], w1);
    v[2] = cmulf(v[2], w2);
    v[3] = cmulf(v[3], w3);
    v[4] = cmulf(v[4], w4);
    v[5] = cmulf(v[5], w5);
    v[6] = cmulf(v[6], w6);
    v[7] = cmulf(v[7], w7);
    v[8] = cmulf(v[8], w8);
    v[9] = cmulf(v[9], w9);
}

// ---------------- middle stages 1 & 2 (smem -> smem) ----------------
__device__ __forceinline__ void fft_mid(float2* bufA, float2* bufB, int bf) {
    // stage 1: m=10
    if (bf < 1000) {
        int j = bf / 10, k = bf - j * 10;
        float2 u[10];
#pragma unroll
        for (int q = 0; q < 10; q++) u[q] = bufA[SKF(bf + q * 1000)];
        float2 v[10];
        dft10(u, v);
        if (j) twiddle9_otf(v, j * 10);
        int ob = k + 100 * j;
#pragma unroll
        for (int t = 0; t < 10; t++) bufB[SKF(ob + 10 * t)] = v[t];
    }
    __syncthreads();
    // stage 2: m=100
    if (bf < 1000) {
        int j = bf / 100, k = bf - j * 100;
        float2 u[10];
#pragma unroll
        for (int q = 0; q < 10; q++) u[q] = bufB[SKF(bf + q * 1000)];
        float2 v[10];
        dft10(u, v);
        if (j) twiddle9_otf(v, j * 100);
        int ob = k + 1000 * j;
#pragma unroll
        for (int t = 0; t < 10; t++) bufA[SKF(ob + 100 * t)] = v[t];
    }
    __syncthreads();
}

// ---------------- forward FFT (global in, Hermitian half out) ----------
__global__ void __launch_bounds__(FFTTHREADS, 1)
fwd_fft_kernel(const float* __restrict__ atom,
               const float* __restrict__ pos,
               const float* __restrict__ clos) {
    extern __shared__ float2 sb[];
    float2* bufA = sb;
    float2* bufB = sb + SBUF;
    int vb = blockIdx.x;
    const float* x;
    float2* out;
    if (vb < NA)           { x = atom + vb * D;        out = Fa_g + vb * F; }
    else if (vb < NA + NS) { x = pos + (vb - NA) * D;  out = Fp_g + (vb - NA) * F; }
    else                   { x = clos;                 out = Fc_g; }

    int bf = threadIdx.x;
    if (bf < 1000) {
        float2 u[10];
#pragma unroll
        for (int q = 0; q < 10; q++) u[q] = make_float2(x[bf + q * 1000], 0.f);
        float2 v[10];
        dft10(u, v);
        if (bf) twiddle9_otf(v, bf);
#pragma unroll
        for (int t = 0; t < 10; t++) bufA[13 * bf + t] = v[t];
    }
    __syncthreads();

    fft_mid(bufA, bufB, bf);

    if (bf < 1000) {
        float2 u[10];
#pragma unroll
        for (int q = 0; q < 10; q++) u[q] = bufA[SKF(bf + q * 1000)];
        float2 v[10];
        dft10(u, v);
#pragma unroll
        for (int t = 0; t < 10; t++) {
            int p = bf + 1000 * t;
            if (p < F) out[p] = v[t];
        }
    }
}

// ---------------- frequency combine: z-split over s -------------------
// z=0: tokens s in [0,64).   z=1: tokens s in [64,128) + rings.
__global__ void combine_kernel(const float* __restrict__ tmask,
                               const float* __restrict__ rmask,
                               const int*   __restrict__ aidx,
                               const int*   __restrict__ rpos) {
    __shared__ float2 s_mi[BG][SHALF];
    __shared__ int   s_rp[BG][NR][2];
    __shared__ float s_rm[BG][NR];
    __shared__ float2 s_fa[NA][128];

    int b0 = blockIdx.y * BG;
    int z  = blockIdx.z;
    int s0 = z * SHALF;
    int tx = threadIdx.x;

    for (int t = tx; t < BG * SHALF; t += 128) {
        int bb = t / SHALF, s = t % SHALF;
        s_mi[bb][s] = make_float2(tmask[(b0 + bb) * NS + s0 + s],
                                  __int_as_float(aidx[(b0 + bb) * NS + s0 + s]));
    }
    if (z == 1) {
        for (int t = tx; t < BG * NR; t += 128) {
            int bb = t / NR, r = t % NR;
            s_rp[bb][r][0] = rpos[((b0 + bb) * NR + r) * 2 + 0];
            s_rp[bb][r][1] = rpos[((b0 + bb) * NR + r) * 2 + 1];
            s_rm[bb][r]    = rmask[(b0 + bb) * NR + r];
        }
    }
    int f = blockIdx.x * 128 + tx;
    if (f < F) {
        for (int i = 0; i < NA; i++) s_fa[i][tx] = Fa_g[i * F + f];
    }
    __syncthreads();
    if (f >= F) return;

    float2 acc[BG];
#pragma unroll
    for (int bb = 0; bb < BG; bb++) acc[bb] = make_float2(0.f, 0.f);

#pragma unroll 4
    for (int s = 0; s < SHALF; s++) {
        float2 fp = Fp_g[(s0 + s) * F + f];
        float nfpy = -fp.y;
#pragma unroll
        for (int bb = 0; bb < BG; bb++) {
            float2 mi = s_mi[bb][s];
            int    a  = __float_as_int(mi.y);
            float2 fa = s_fa[a][tx];
            float p = mi.x * fa.x;
            float q = mi.x * fa.y;
            acc[bb].x += p * fp.x;
            acc[bb].x += q * nfpy;
            acc[bb].y += p * fp.y;
            acc[bb].y += q * fp.x;
        }
    }
    if (z == 1) {
        float2 fc = Fc_g[f];
#pragma unroll
        for (int bb = 0; bb < BG; bb++) {
            for (int r = 0; r < NR; r++) {
                float2 f0 = Fp_g[s_rp[bb][r][0] * F + f];
                float2 f1 = Fp_g[s_rp[bb][r][1] * F + f];
                float2 t  = cmulf(cmulf(f0, f1), fc);
                float mm  = s_rm[bb][r];
                acc[bb].x += mm * t.x;
                acc[bb].y += mm * t.y;
            }
        }
    }
#pragma unroll
    for (int bb = 0; bb < BG; bb++)
        Freq_g[z][(b0 + bb) * F + f] = acc[bb];
}

// ---------------- inverse FFT (sum partials, Hermitian, conj trick) ----
__global__ void __launch_bounds__(FFTTHREADS, 1)
inv_fft_kernel() {
    extern __shared__ float2 sb[];
    float2* bufA = sb;
    float2* bufB = sb + SBUF;
    int b = blockIdx.x;
    const float2* in0 = Freq_g[0] + b * F;
    const float2* in1 = Freq_g[1] + b * F;

    int bf = threadIdx.x;
    if (bf < 1000) {
        float2 u[10];
#pragma unroll
        for (int q = 0; q < 10; q++) {
            int i = bf + q * 1000;
            int ii = (i < F) ? i : (D - i);
            float2 za = in0[ii];
            float2 zb = in1[ii];
            float2 z = make_float2(za.x + zb.x, za.y + zb.y);
            if (i < F) z.y = -z.y;     // conj for lower half
            u[q] = z;
        }
        float2 v[10];
        dft10(u, v);
        if (bf) twiddle9_otf(v, bf);
#pragma unroll
        for (int t = 0; t < 10; t++) bufA[13 * bf + t] = v[t];
    }
    __syncthreads();

    fft_mid(bufA, bufB, bf);

    if (bf < 1000) {
        float2 u[10];
#pragma unroll
        for (int q = 0; q < 10; q++) u[q] = bufA[SKF(bf + q * 1000)];
        float2 v[10];
        dft10(u, v);
        const float inv = 1.0f / (float)D;
        float* mo = Mol_g + b * D;
#pragma unroll
        for (int t = 0; t < 10; t++) mo[bf + 1000 * t] = v[t].x * inv;
    }
}

// ---------------- projection ----------------
__global__ void init_out_kernel(const float* __restrict__ bias,
                                float* __restrict__ out) {
    int b = blockIdx.x, p = threadIdx.x;
    out[b * NP + p] = bias[p];
}

__global__ void __launch_bounds__(256)
proj_kernel(const float* __restrict__ Wm, float* __restrict__ out) {
    __shared__ float sA[64][DLEN + 1];
    __shared__ float sW[64][DLEN + 1];
    int pb = blockIdx.x;
    int ds = blockIdx.y;
    int dbase = ds * DLEN;
    int tid = threadIdx.x;

    for (int t = tid; t < 64 * DLEN; t += 256) {
        int r = t / DLEN, dd = t - r * DLEN;
        sA[r][dd] = Mol_g[r * D + dbase + dd];
    }
    for (int t = tid; t < 64 * DLEN; t += 256) {
        int r = t / DLEN, dd = t - r * DLEN;
        sW[r][dd] = Wm[(pb * 64 + r) * D + dbase + dd];
    }
    __syncthreads();

    int tx = tid & 15;
    int ty = tid >> 4;
    float acc[4][4];
#pragma unroll
    for (int i = 0; i < 4; i++)
#pragma unroll
        for (int j = 0; j < 4; j++) acc[i][j] = 0.f;

#pragma unroll 8
    for (int dd = 0; dd < DLEN; dd++) {
        float a0 = sA[ty * 4 + 0][dd];
        float a1 = sA[ty * 4 + 1][dd];
        float a2 = sA[ty * 4 + 2][dd];
        float a3 = sA[ty * 4 + 3][dd];
        float w0 = sW[tx * 4 + 0][dd];
        float w1 = sW[tx * 4 + 1][dd];
        float w2 = sW[tx * 4 + 2][dd];
        float w3 = sW[tx * 4 + 3][dd];
        acc[0][0] += a0 * w0; acc[0][1] += a0 * w1; acc[0][2] += a0 * w2; acc[0][3] += a0 * w3;
        acc[1][0] += a1 * w0; acc[1][1] += a1 * w1; acc[1][2] += a1 * w2; acc[1][3] += a1 * w3;
        acc[2][0] += a2 * w0; acc[2][1] += a2 * w1; acc[2][2] += a2 * w2; acc[2][3] += a2 * w3;
        acc[3][0] += a3 * w0; acc[3][1] += a3 * w1; acc[3][2] += a3 * w2; acc[3][3] += a3 * w3;
    }
#pragma unroll
    for (int i = 0; i < 4; i++) {
        int b = ty * 4 + i;
#pragma unroll
        for (int j = 0; j < 4; j++) {
            int p = pb * 64 + tx * 4 + j;
            atomicAdd(&out[b * NP + p], acc[i][j]);
        }
    }
}

// ---------------- launch ----------------
extern "C" void kernel_launch(void* const* d_in, const int* in_sizes, int n_in,
                              void* d_out, int out_size) {
    const float* atom  = (const float*)d_in[0];
    const float* pos   = (const float*)d_in[1];
    const float* clos  = (const float*)d_in[2];
    const float* Wm    = (const float*)d_in[3];
    const float* bias  = (const float*)d_in[4];
    const float* tmask = (const float*)d_in[5];
    const float* rmask = (const float*)d_in[6];
    const int*   aidx  = (const int*)d_in[7];
    const int*   rpos  = (const int*)d_in[8];
    float* out = (float*)d_out;

    size_t smem = 2 * (size_t)SBUF * sizeof(float2);   // 208000 B
    cudaFuncSetAttribute(fwd_fft_kernel,
                         cudaFuncAttributeMaxDynamicSharedMemorySize, (int)smem);
    cudaFuncSetAttribute(inv_fft_kernel,
                         cudaFuncAttributeMaxDynamicSharedMemorySize, (int)smem);

    fwd_fft_kernel<<<NA + NS + 1, FFTTHREADS, smem>>>(atom, pos, clos);

    dim3 cg((F + 127) / 128, NB / BG, 2);
    combine_kernel<<<cg, 128>>>(tmask, rmask, aidx, rpos);

    inv_fft_kernel<<<NB, FFTTHREADS, smem>>>();

    init_out_kernel<<<NB, NP>>>(bias, out);
    dim3 pg(NP / 64, DSPLIT);
    proj_kernel<<<pg, 256>>>(Wm, out);
}